// round 11
// baseline (speedup 1.0000x reference)
#include <cuda_runtime.h>
#include <cuda_bf16.h>
#include <math.h>
#include <stdint.h>

#define Bn 128
#define Tn 512
#define Dn 256
#define Vn 4096
#define Sn 512

// ---------------------------------------------------------------------------
// Device scratch (no cudaMalloc allowed)
// ---------------------------------------------------------------------------
__device__ float          g_pre[Bn * Tn * Dn];          // fp32 pre-activations
__device__ __nv_bfloat16  g_hH[Bn * Tn * Dn];           // hidden hi
__device__ __nv_bfloat16  g_hL[Bn * Tn * Dn];           // hidden lo
__device__ __nv_bfloat16  g_embH[Vn * Dn], g_embL[Vn * Dn];
__device__ __nv_bfloat16  g_w0H[Dn * Dn],  g_w0L[Dn * Dn];
__device__ __nv_bfloat16  g_w1H[Dn * Dn],  g_w1L[Dn * Dn];
__device__ __nv_bfloat16  g_whH[Sn * Dn],  g_whL[Sn * Dn];

// ---------------------------------------------------------------------------
// mma.sync / ldmatrix / cp.async helpers (sm_80-era PTX: legal under compute_103)
// ---------------------------------------------------------------------------
__device__ __forceinline__ uint32_t smem_u32(const void* p) {
    uint32_t a;
    asm("{ .reg .u64 t; cvta.to.shared.u64 t, %1; cvt.u32.u64 %0, t; }"
        : "=r"(a) : "l"(p));
    return a;
}
__device__ __forceinline__ void ldsm4(uint32_t r[4], uint32_t addr) {
    asm volatile("ldmatrix.sync.aligned.m8n8.x4.shared.b16 {%0,%1,%2,%3}, [%4];"
                 : "=r"(r[0]), "=r"(r[1]), "=r"(r[2]), "=r"(r[3]) : "r"(addr));
}
__device__ __forceinline__ void mma_bf16(float d[4], const uint32_t a[4],
                                         const uint32_t b[2]) {
    asm volatile(
        "mma.sync.aligned.m16n8k16.row.col.f32.bf16.bf16.f32 "
        "{%0,%1,%2,%3}, {%4,%5,%6,%7}, {%8,%9}, {%0,%1,%2,%3};"
        : "+f"(d[0]), "+f"(d[1]), "+f"(d[2]), "+f"(d[3])
        : "r"(a[0]), "r"(a[1]), "r"(a[2]), "r"(a[3]), "r"(b[0]), "r"(b[1]));
}
__device__ __forceinline__ void cpa16(uint32_t saddr, const void* g) {
    asm volatile("cp.async.cg.shared.global [%0], [%1], 16;"
                 :: "r"(saddr), "l"(g) : "memory");
}
#define CPA_COMMIT() asm volatile("cp.async.commit_group;" ::: "memory")
#define CPA_WAIT2()  asm volatile("cp.async.wait_group 2;" ::: "memory")

// ---------------------------------------------------------------------------
// Tensor-core GEMM (round-8, passing):
// C[M][N] = (AH+AL)[M][256] * (BH+BL)[N][256]^T (+b1[n]+b2[n])
// ---------------------------------------------------------------------------
#define A_PITCH 528
#define B_PITCH 80
#define SM_AH   0
#define SM_AL   (128 * A_PITCH)
#define SM_B    (2 * 128 * A_PITCH)            // 135168
#define B_SEG   (128 * B_PITCH)                // 10240
#define NSTAGE  4
#define GEMM_SMEM (SM_B + NSTAGE * 2 * B_SEG)  // 217088 B

__global__ __launch_bounds__(256, 1) void gemm_mma(
    const __nv_bfloat16* __restrict__ AH, const __nv_bfloat16* __restrict__ AL,
    const int* __restrict__ ids,
    const __nv_bfloat16* __restrict__ BH, const __nv_bfloat16* __restrict__ BL,
    const float* __restrict__ b1, const float* __restrict__ b2,
    float* __restrict__ C, int N)
{
    extern __shared__ char gsm[];
    const uint32_t sb = smem_u32(gsm);

    const int tid = threadIdx.x;
    const int wid = tid >> 5, lane = tid & 31;
    const int warp_m = wid >> 2;
    const int warp_n = wid & 3;
    const int m0 = blockIdx.x * 128;

#pragma unroll 4
    for (int i = tid; i < 4096; i += 256) {
        int row = i >> 5, seg = i & 31;
        int src = ids ? __ldg(ids + m0 + row) : (m0 + row);
        cpa16(sb + SM_AH + row * A_PITCH + seg * 16,
              AH + (size_t)src * 256 + seg * 8);
        cpa16(sb + SM_AL + row * A_PITCH + seg * 16,
              AL + (size_t)src * 256 + seg * 8);
    }
    CPA_COMMIT();

    const int aRow = warp_m * 64 + (lane & 15);
    const uint32_t aOff = (uint32_t)aRow * A_PITCH + ((lane >> 4) * 8) * 2;
    const uint32_t aBaseH = sb + SM_AH + aOff;
    const uint32_t aBaseL = sb + SM_AL + aOff;
    const int bN = warp_n * 32 + (lane & 7) + ((lane >> 4) << 3);
    const uint32_t bOff = (uint32_t)bN * B_PITCH + ((lane >> 3) & 1) * 16;

    const int lrow = tid >> 1;
    const int lseg = (tid & 1) * 2;
    const uint32_t bstW = sb + SM_B + lrow * B_PITCH + lseg * 16;

    const int nTiles = N >> 7;
#pragma unroll 1
    for (int nt = 0; nt < nTiles; nt++) {
        const int n0 = nt << 7;

        float acc[4][4][4];
#pragma unroll
        for (int i = 0; i < 4; i++)
#pragma unroll
            for (int j = 0; j < 4; j++)
#pragma unroll
                for (int r = 0; r < 4; r++) acc[i][j][r] = 0.f;

#pragma unroll
        for (int pc = 0; pc < 3; pc++) {
            const __nv_bfloat16* gh =
                BH + (size_t)(n0 + lrow) * 256 + pc * 32 + lseg * 8;
            const __nv_bfloat16* gl =
                BL + (size_t)(n0 + lrow) * 256 + pc * 32 + lseg * 8;
            uint32_t d = bstW + pc * (2 * B_SEG);
            cpa16(d, gh);             cpa16(d + 16, gh + 8);
            cpa16(d + B_SEG, gl);     cpa16(d + B_SEG + 16, gl + 8);
            CPA_COMMIT();
        }

#pragma unroll 1
        for (int kc = 0; kc < 8; kc++) {
            CPA_WAIT2();
            __syncthreads();

            const uint32_t hiB = sb + SM_B + (uint32_t)(kc & 3) * (2 * B_SEG) + bOff;
            const uint32_t loB = hiB + B_SEG;

            if (kc < 5) {
                const __nv_bfloat16* gh =
                    BH + (size_t)(n0 + lrow) * 256 + (kc + 3) * 32 + lseg * 8;
                const __nv_bfloat16* gl =
                    BL + (size_t)(n0 + lrow) * 256 + (kc + 3) * 32 + lseg * 8;
                uint32_t d = bstW + (uint32_t)((kc + 3) & 3) * (2 * B_SEG);
                cpa16(d, gh);             cpa16(d + 16, gh + 8);
                cpa16(d + B_SEG, gl);     cpa16(d + B_SEG + 16, gl + 8);
            }
            CPA_COMMIT();

#pragma unroll
            for (int kk = 0; kk < 2; kk++) {
                const uint32_t aK = (uint32_t)(kc * 2 + kk) * 32;
                uint32_t aH[4][4], aL[4][4];
#pragma unroll
                for (int i = 0; i < 4; i++) {
                    ldsm4(aH[i], aBaseH + i * (16 * A_PITCH) + aK);
                    ldsm4(aL[i], aBaseL + i * (16 * A_PITCH) + aK);
                }
                uint32_t bH[2][4], bL[2][4];
#pragma unroll
                for (int p = 0; p < 2; p++) {
                    uint32_t o = (uint32_t)p * (16 * B_PITCH) + (uint32_t)kk * 32;
                    ldsm4(bH[p], hiB + o);
                    ldsm4(bL[p], loB + o);
                }
#pragma unroll
                for (int i = 0; i < 4; i++)
#pragma unroll
                    for (int j = 0; j < 4; j++)
                        mma_bf16(acc[i][j], aH[i], &bH[j >> 1][(j & 1) * 2]);
#pragma unroll
                for (int i = 0; i < 4; i++)
#pragma unroll
                    for (int j = 0; j < 4; j++)
                        mma_bf16(acc[i][j], aH[i], &bL[j >> 1][(j & 1) * 2]);
#pragma unroll
                for (int i = 0; i < 4; i++)
#pragma unroll
                    for (int j = 0; j < 4; j++)
                        mma_bf16(acc[i][j], aL[i], &bH[j >> 1][(j & 1) * 2]);
            }
        }

        const int rBase = m0 + warp_m * 64 + (lane >> 2);
        const int cBase = n0 + warp_n * 32 + (lane & 3) * 2;
#pragma unroll
        for (int j = 0; j < 4; j++) {
            const int col = cBase + j * 8;
            float bb0 = 0.f, bb1 = 0.f;
            if (b1) {
                bb0 = b1[col] + b2[col];
                bb1 = b1[col + 1] + b2[col + 1];
            }
#pragma unroll
            for (int i = 0; i < 4; i++) {
                const int row = rBase + i * 16;
                float2 v0 = make_float2(acc[i][j][0] + bb0, acc[i][j][1] + bb1);
                float2 v1 = make_float2(acc[i][j][2] + bb0, acc[i][j][3] + bb1);
                *(float2*)(C + (size_t)row * N + col) = v0;
                *(float2*)(C + (size_t)(row + 8) * N + col) = v1;
            }
        }
    }
}

// ---------------------------------------------------------------------------
// fp32 -> bf16 hi/lo split converter
// ---------------------------------------------------------------------------
__global__ void conv_split(const float* __restrict__ src,
                           __nv_bfloat16* __restrict__ hi,
                           __nv_bfloat16* __restrict__ lo, int n)
{
    int i = blockIdx.x * 256 + threadIdx.x;
    if (i < n) {
        float v = src[i];
        __nv_bfloat16 h = __float2bfloat16(v);
        hi[i] = h;
        lo[i] = __float2bfloat16(v - __bfloat162float(h));
    }
}

// ---------------------------------------------------------------------------
// Recurrence v8: 512 threads, intra-warp K-split pair + shfl combine.
//   h_t = tanh(pre_t + W_hh @ h_{t-1})
// Thread pair (2j, 2j+1) IN THE SAME WARP owns row j's two K-halves:
//   t = threadIdx.x; j = t>>1; half = t&1; K-cols [half*128, half*128+128)
//   - 88 cols in 22 float4 registers (512thr * ~118 regs < 64K RF, no spill)
//   - 40 cols in smem (20 float2 pairs, transposed; half1 array offset +64B
//     so even/odd lanes hit disjoint bank halves -> conflict-free)
// Combine = one __shfl_xor(ps,1). Tail split: even thread writes smem h,
// odd thread emits bf16 hi/lo to global. One barrier/step (double-buffered h),
// exactly like round-4, but with 4 warps/SMSP to overlap LDS with FFMA.
// ---------------------------------------------------------------------------
#define RQ 22          // float4 of W in registers per thread (88 cols)
#define SP 20          // float2 W pairs in smem per half     (40 cols)
#define SM_WA 0                        // half0 pairs [SP][256] float2
#define SM_WB (SP * 256 * 8 + 64)      // half1 pairs, +64B bank skew
#define SM_HA (2 * SP * 256 * 8 + 64)  // hA (1024B)
#define SM_HB (SM_HA + 1024)           // hB
#define RECUR_SMEM (SM_HB + 1024)      // 84032 B

extern __shared__ float smem_r[];

__global__ void __launch_bounds__(512, 1) rnn_recur(
    const float* __restrict__ pre,        // [B][T][D]
    const float* __restrict__ Whh,        // [D][D]
    __nv_bfloat16* __restrict__ houtH,    // [B][T][D]
    __nv_bfloat16* __restrict__ houtL)
{
    char* smb = (char*)smem_r;
    float2* WpA = (float2*)(smb + SM_WA);
    float2* WpB = (float2*)(smb + SM_WB);
    float*  hA  = (float*)(smb + SM_HA);
    float*  hB  = (float*)(smb + SM_HB);

    const int tid  = threadIdx.x;
    const int j    = tid >> 1;
    const int half = tid & 1;
    const int b    = blockIdx.x;

    // Register W: row j, cols [half*128, half*128+88)
    float4 wr[RQ];
    {
        const float4* wrow =
            (const float4*)(Whh + (size_t)j * 256 + half * 128);
#pragma unroll
        for (int q = 0; q < RQ; q++) wr[q] = wrow[q];
    }
    // Smem W transposed pairs: Wp{A,B}[p][r] = (W[r][c], W[r][c+1]),
    //   c = half*128 + 88 + 2p, p in [0,20)
    for (int i = tid; i < 2 * SP * 256; i += 512) {
        int hh = i / (SP * 256);
        int rem = i - hh * (SP * 256);
        int p = rem >> 8, r = rem & 255;
        float2 val = *(const float2*)(Whh + (size_t)r * 256 + hh * 128 + 88 + 2 * p);
        (hh ? WpB : WpA)[p * 256 + r] = val;
    }

    if (half == 0) hA[j] = 0.f;
    __syncthreads();

    const float*   prow = pre   + ((size_t)b * Tn) * Dn;
    __nv_bfloat16* ohr  = houtH + ((size_t)b * Tn) * Dn;
    __nv_bfloat16* olr  = houtL + ((size_t)b * Tn) * Dn;

    const float2* WpJ = (half ? WpB : WpA) + j;
    const int hOff = half * 32;            // this half's h, in float4 units

    float pcur = prow[j];

#pragma unroll 1
    for (int step = 0; step < Tn; step += 2) {
#pragma unroll
        for (int sub = 0; sub < 2; sub++) {
            const float4* hb =
                ((const float4*)(sub ? hB : hA)) + hOff;
            float* hnext = sub ? hA : hB;

            float a0 = 0.f, a1 = 0.f, a2 = 0.f, a3 = 0.f;
#pragma unroll
            for (int q = 0; q < RQ; q++) {
                float4 h = hb[q];
                float4 w = wr[q];
                a0 = fmaf(w.x, h.x, a0);
                a1 = fmaf(w.y, h.y, a1);
                a2 = fmaf(w.z, h.z, a2);
                a3 = fmaf(w.w, h.w, a3);
            }
#pragma unroll
            for (int q = 0; q < 10; q++) {
                float4 h  = hb[RQ + q];
                float2 w0 = WpJ[(2 * q + 0) * 256];
                float2 w1 = WpJ[(2 * q + 1) * 256];
                a0 = fmaf(w0.x, h.x, a0);
                a1 = fmaf(w0.y, h.y, a1);
                a2 = fmaf(w1.x, h.z, a2);
                a3 = fmaf(w1.y, h.w, a3);
            }
            float ps = (a0 + a1) + (a2 + a3);
            float s  = ps + __shfl_xor_sync(0xFFFFFFFFu, ps, 1);

            float pnext = (step + sub + 1 < Tn) ? prow[Dn + j] : 0.f;

            float v = tanhf(pcur + s);
            if (half == 0) {
                hnext[j] = v;              // smem h for next step
            } else {
                __nv_bfloat16 vh = __float2bfloat16(v);
                ohr[j] = vh;               // global bf16 hi/lo emit
                olr[j] = __float2bfloat16(v - __bfloat162float(vh));
            }
            pcur = pnext;
            __syncthreads();

            prow += Dn; ohr += Dn; olr += Dn;
        }
    }
}

// ---------------------------------------------------------------------------
extern "C" void kernel_launch(void* const* d_in, const int* in_sizes, int n_in,
                              void* d_out, int out_size)
{
    (void)in_sizes; (void)n_in; (void)out_size;

    const int*   ids   = (const int*)  d_in[0];
    const float* emb   = (const float*)d_in[1];
    const float* Wih0  = (const float*)d_in[2];
    const float* Whh0  = (const float*)d_in[3];
    const float* bih0  = (const float*)d_in[4];
    const float* bhh0  = (const float*)d_in[5];
    const float* Wih1  = (const float*)d_in[6];
    const float* Whh1  = (const float*)d_in[7];
    const float* bih1  = (const float*)d_in[8];
    const float* bhh1  = (const float*)d_in[9];
    const float* Whead = (const float*)d_in[10];
    float* out = (float*)d_out;

    float *pre;           cudaGetSymbolAddress((void**)&pre,  g_pre);
    __nv_bfloat16 *hH;    cudaGetSymbolAddress((void**)&hH,   g_hH);
    __nv_bfloat16 *hL;    cudaGetSymbolAddress((void**)&hL,   g_hL);
    __nv_bfloat16 *embH;  cudaGetSymbolAddress((void**)&embH, g_embH);
    __nv_bfloat16 *embL;  cudaGetSymbolAddress((void**)&embL, g_embL);
    __nv_bfloat16 *w0H;   cudaGetSymbolAddress((void**)&w0H,  g_w0H);
    __nv_bfloat16 *w0L;   cudaGetSymbolAddress((void**)&w0L,  g_w0L);
    __nv_bfloat16 *w1H;   cudaGetSymbolAddress((void**)&w1H,  g_w1H);
    __nv_bfloat16 *w1L;   cudaGetSymbolAddress((void**)&w1L,  g_w1L);
    __nv_bfloat16 *whH;   cudaGetSymbolAddress((void**)&whH,  g_whH);
    __nv_bfloat16 *whL;   cudaGetSymbolAddress((void**)&whL,  g_whL);

    cudaFuncSetAttribute(rnn_recur, cudaFuncAttributeMaxDynamicSharedMemorySize,
                         RECUR_SMEM);
    cudaFuncSetAttribute(gemm_mma, cudaFuncAttributeMaxDynamicSharedMemorySize,
                         GEMM_SMEM);

    // Weight / embedding bf16 hi-lo splits
    conv_split<<<(Vn * Dn + 255) / 256, 256>>>(emb,   embH, embL, Vn * Dn);
    conv_split<<<(Dn * Dn + 255) / 256, 256>>>(Wih0,  w0H,  w0L,  Dn * Dn);
    conv_split<<<(Dn * Dn + 255) / 256, 256>>>(Wih1,  w1H,  w1L,  Dn * Dn);
    conv_split<<<(Sn * Dn + 255) / 256, 256>>>(Whead, whH,  whL,  Sn * Dn);

    const int M = Bn * Tn;   // 65536

    // pre0 = emb[ids] @ W_ih0^T + (b_ih0 + b_hh0)
    gemm_mma<<<M / 128, 256, GEMM_SMEM>>>(embH, embL, ids, w0H, w0L,
                                          bih0, bhh0, pre, Dn);
    // h1 recurrence (emits bf16 hi/lo)
    rnn_recur<<<Bn, 512, RECUR_SMEM>>>(pre, Whh0, hH, hL);
    // pre1 = h1 @ W_ih1^T + (b_ih1 + b_hh1)
    gemm_mma<<<M / 128, 256, GEMM_SMEM>>>(hH, hL, nullptr, w1H, w1L,
                                          bih1, bhh1, pre, Dn);
    // h2 recurrence
    rnn_recur<<<Bn, 512, RECUR_SMEM>>>(pre, Whh1, hH, hL);
    // logits = h2 @ W_head^T
    gemm_mma<<<M / 128, 256, GEMM_SMEM>>>(hH, hL, nullptr, whH, whL,
                                          nullptr, nullptr, out, Sn);
}

// round 12
// speedup vs baseline: 1.4217x; 1.4217x over previous
#include <cuda_runtime.h>
#include <cuda_bf16.h>
#include <math.h>
#include <stdint.h>

#define Bn 128
#define Tn 512
#define Dn 256
#define Vn 4096
#define Sn 512

// ---------------------------------------------------------------------------
// Device scratch (no cudaMalloc allowed)
// ---------------------------------------------------------------------------
__device__ float          g_pre[Bn * Tn * Dn];          // fp32 pre-activations
__device__ __nv_bfloat16  g_hH[Bn * Tn * Dn];           // hidden hi
__device__ __nv_bfloat16  g_hL[Bn * Tn * Dn];           // hidden lo
__device__ __nv_bfloat16  g_embH[Vn * Dn], g_embL[Vn * Dn];
__device__ __nv_bfloat16  g_w0H[Dn * Dn],  g_w0L[Dn * Dn];
__device__ __nv_bfloat16  g_w1H[Dn * Dn],  g_w1L[Dn * Dn];
__device__ __nv_bfloat16  g_whH[Sn * Dn],  g_whL[Sn * Dn];

// ---------------------------------------------------------------------------
// mma.sync / ldmatrix / cp.async helpers (sm_80-era PTX: legal under compute_103)
// ---------------------------------------------------------------------------
__device__ __forceinline__ uint32_t smem_u32(const void* p) {
    uint32_t a;
    asm("{ .reg .u64 t; cvta.to.shared.u64 t, %1; cvt.u32.u64 %0, t; }"
        : "=r"(a) : "l"(p));
    return a;
}
__device__ __forceinline__ void ldsm4(uint32_t r[4], uint32_t addr) {
    asm volatile("ldmatrix.sync.aligned.m8n8.x4.shared.b16 {%0,%1,%2,%3}, [%4];"
                 : "=r"(r[0]), "=r"(r[1]), "=r"(r[2]), "=r"(r[3]) : "r"(addr));
}
__device__ __forceinline__ void mma_bf16(float d[4], const uint32_t a[4],
                                         const uint32_t b[2]) {
    asm volatile(
        "mma.sync.aligned.m16n8k16.row.col.f32.bf16.bf16.f32 "
        "{%0,%1,%2,%3}, {%4,%5,%6,%7}, {%8,%9}, {%0,%1,%2,%3};"
        : "+f"(d[0]), "+f"(d[1]), "+f"(d[2]), "+f"(d[3])
        : "r"(a[0]), "r"(a[1]), "r"(a[2]), "r"(a[3]), "r"(b[0]), "r"(b[1]));
}
__device__ __forceinline__ void cpa16(uint32_t saddr, const void* g) {
    asm volatile("cp.async.cg.shared.global [%0], [%1], 16;"
                 :: "r"(saddr), "l"(g) : "memory");
}
#define CPA_COMMIT() asm volatile("cp.async.commit_group;" ::: "memory")
#define CPA_WAIT2()  asm volatile("cp.async.wait_group 2;" ::: "memory")

// Fast accurate-enough tanh: MUFU.EX2 + fast divide (abs err ~1e-7).
__device__ __forceinline__ float fast_tanh(float z) {
    float t = __expf(-2.f * fabsf(z));
    float r = __fdividef(t, 1.f + t);
    return copysignf(fmaf(-2.f, r, 1.f), z);
}

// ---------------------------------------------------------------------------
// Tensor-core GEMM (round-8, passing):
// C[M][N] = (AH+AL)[M][256] * (BH+BL)[N][256]^T (+b1[n]+b2[n])
// ---------------------------------------------------------------------------
#define A_PITCH 528
#define B_PITCH 80
#define SM_AH   0
#define SM_AL   (128 * A_PITCH)
#define SM_B    (2 * 128 * A_PITCH)            // 135168
#define B_SEG   (128 * B_PITCH)                // 10240
#define NSTAGE  4
#define GEMM_SMEM (SM_B + NSTAGE * 2 * B_SEG)  // 217088 B

__global__ __launch_bounds__(256, 1) void gemm_mma(
    const __nv_bfloat16* __restrict__ AH, const __nv_bfloat16* __restrict__ AL,
    const int* __restrict__ ids,
    const __nv_bfloat16* __restrict__ BH, const __nv_bfloat16* __restrict__ BL,
    const float* __restrict__ b1, const float* __restrict__ b2,
    float* __restrict__ C, int N)
{
    extern __shared__ char gsm[];
    const uint32_t sb = smem_u32(gsm);

    const int tid = threadIdx.x;
    const int wid = tid >> 5, lane = tid & 31;
    const int warp_m = wid >> 2;
    const int warp_n = wid & 3;
    const int m0 = blockIdx.x * 128;

#pragma unroll 4
    for (int i = tid; i < 4096; i += 256) {
        int row = i >> 5, seg = i & 31;
        int src = ids ? __ldg(ids + m0 + row) : (m0 + row);
        cpa16(sb + SM_AH + row * A_PITCH + seg * 16,
              AH + (size_t)src * 256 + seg * 8);
        cpa16(sb + SM_AL + row * A_PITCH + seg * 16,
              AL + (size_t)src * 256 + seg * 8);
    }
    CPA_COMMIT();

    const int aRow = warp_m * 64 + (lane & 15);
    const uint32_t aOff = (uint32_t)aRow * A_PITCH + ((lane >> 4) * 8) * 2;
    const uint32_t aBaseH = sb + SM_AH + aOff;
    const uint32_t aBaseL = sb + SM_AL + aOff;
    const int bN = warp_n * 32 + (lane & 7) + ((lane >> 4) << 3);
    const uint32_t bOff = (uint32_t)bN * B_PITCH + ((lane >> 3) & 1) * 16;

    const int lrow = tid >> 1;
    const int lseg = (tid & 1) * 2;
    const uint32_t bstW = sb + SM_B + lrow * B_PITCH + lseg * 16;

    const int nTiles = N >> 7;
#pragma unroll 1
    for (int nt = 0; nt < nTiles; nt++) {
        const int n0 = nt << 7;

        float acc[4][4][4];
#pragma unroll
        for (int i = 0; i < 4; i++)
#pragma unroll
            for (int j = 0; j < 4; j++)
#pragma unroll
                for (int r = 0; r < 4; r++) acc[i][j][r] = 0.f;

#pragma unroll
        for (int pc = 0; pc < 3; pc++) {
            const __nv_bfloat16* gh =
                BH + (size_t)(n0 + lrow) * 256 + pc * 32 + lseg * 8;
            const __nv_bfloat16* gl =
                BL + (size_t)(n0 + lrow) * 256 + pc * 32 + lseg * 8;
            uint32_t d = bstW + pc * (2 * B_SEG);
            cpa16(d, gh);             cpa16(d + 16, gh + 8);
            cpa16(d + B_SEG, gl);     cpa16(d + B_SEG + 16, gl + 8);
            CPA_COMMIT();
        }

#pragma unroll 1
        for (int kc = 0; kc < 8; kc++) {
            CPA_WAIT2();
            __syncthreads();

            const uint32_t hiB = sb + SM_B + (uint32_t)(kc & 3) * (2 * B_SEG) + bOff;
            const uint32_t loB = hiB + B_SEG;

            if (kc < 5) {
                const __nv_bfloat16* gh =
                    BH + (size_t)(n0 + lrow) * 256 + (kc + 3) * 32 + lseg * 8;
                const __nv_bfloat16* gl =
                    BL + (size_t)(n0 + lrow) * 256 + (kc + 3) * 32 + lseg * 8;
                uint32_t d = bstW + (uint32_t)((kc + 3) & 3) * (2 * B_SEG);
                cpa16(d, gh);             cpa16(d + 16, gh + 8);
                cpa16(d + B_SEG, gl);     cpa16(d + B_SEG + 16, gl + 8);
            }
            CPA_COMMIT();

#pragma unroll
            for (int kk = 0; kk < 2; kk++) {
                const uint32_t aK = (uint32_t)(kc * 2 + kk) * 32;
                uint32_t aH[4][4], aL[4][4];
#pragma unroll
                for (int i = 0; i < 4; i++) {
                    ldsm4(aH[i], aBaseH + i * (16 * A_PITCH) + aK);
                    ldsm4(aL[i], aBaseL + i * (16 * A_PITCH) + aK);
                }
                uint32_t bH[2][4], bL[2][4];
#pragma unroll
                for (int p = 0; p < 2; p++) {
                    uint32_t o = (uint32_t)p * (16 * B_PITCH) + (uint32_t)kk * 32;
                    ldsm4(bH[p], hiB + o);
                    ldsm4(bL[p], loB + o);
                }
#pragma unroll
                for (int i = 0; i < 4; i++)
#pragma unroll
                    for (int j = 0; j < 4; j++)
                        mma_bf16(acc[i][j], aH[i], &bH[j >> 1][(j & 1) * 2]);
#pragma unroll
                for (int i = 0; i < 4; i++)
#pragma unroll
                    for (int j = 0; j < 4; j++)
                        mma_bf16(acc[i][j], aH[i], &bL[j >> 1][(j & 1) * 2]);
#pragma unroll
                for (int i = 0; i < 4; i++)
#pragma unroll
                    for (int j = 0; j < 4; j++)
                        mma_bf16(acc[i][j], aL[i], &bH[j >> 1][(j & 1) * 2]);
            }
        }

        const int rBase = m0 + warp_m * 64 + (lane >> 2);
        const int cBase = n0 + warp_n * 32 + (lane & 3) * 2;
#pragma unroll
        for (int j = 0; j < 4; j++) {
            const int col = cBase + j * 8;
            float bb0 = 0.f, bb1 = 0.f;
            if (b1) {
                bb0 = b1[col] + b2[col];
                bb1 = b1[col + 1] + b2[col + 1];
            }
#pragma unroll
            for (int i = 0; i < 4; i++) {
                const int row = rBase + i * 16;
                float2 v0 = make_float2(acc[i][j][0] + bb0, acc[i][j][1] + bb1);
                float2 v1 = make_float2(acc[i][j][2] + bb0, acc[i][j][3] + bb1);
                *(float2*)(C + (size_t)row * N + col) = v0;
                *(float2*)(C + (size_t)(row + 8) * N + col) = v1;
            }
        }
    }
}

// ---------------------------------------------------------------------------
// fp32 -> bf16 hi/lo split converter
// ---------------------------------------------------------------------------
__global__ void conv_split(const float* __restrict__ src,
                           __nv_bfloat16* __restrict__ hi,
                           __nv_bfloat16* __restrict__ lo, int n)
{
    int i = blockIdx.x * 256 + threadIdx.x;
    if (i < n) {
        float v = src[i];
        __nv_bfloat16 h = __float2bfloat16(v);
        hi[i] = h;
        lo[i] = __float2bfloat16(v - __bfloat162float(h));
    }
}

// ---------------------------------------------------------------------------
// Recurrence v9: round-4 structure (proven optimal) + critical-path trims:
//   (a) fast_tanh (MUFU.EX2 + fast div) replaces libm tanhf (~100 cyc saved
//       on the serial path between dot-product and barrier, every step)
//   (b) bf16 hi/lo global emit DEFERRED to after the barrier so the cvt/STG
//       overlap the next step's dot-product issue instead of delaying arrival
// Thread j owns output row j: W[j][0:192] in 48 float4 registers,
// W[:][192:256] via smem pitch-17-float4; h double-buffered, 1 barrier/step.
// ---------------------------------------------------------------------------
#define WREG 48
#define WSMQ 16
#define WPITCH4 17

__device__ __forceinline__ float rnn_dot(
    const float4* __restrict__ wr, const float4* __restrict__ wsr,
    const float4* __restrict__ hb)
{
    float a0 = 0.f, a1 = 0.f, a2 = 0.f, a3 = 0.f;
#pragma unroll
    for (int q = 0; q < WREG; q++) {
        float4 h = hb[q];
        float4 w = wr[q];
        a0 = fmaf(w.x, h.x, a0);
        a1 = fmaf(w.y, h.y, a1);
        a2 = fmaf(w.z, h.z, a2);
        a3 = fmaf(w.w, h.w, a3);
    }
#pragma unroll
    for (int q = 0; q < WSMQ; q++) {
        float4 h = hb[WREG + q];
        float4 w = wsr[q];
        a0 = fmaf(w.x, h.x, a0);
        a1 = fmaf(w.y, h.y, a1);
        a2 = fmaf(w.z, h.z, a2);
        a3 = fmaf(w.w, h.w, a3);
    }
    return (a0 + a1) + (a2 + a3);
}

extern __shared__ float smem_r[];

__global__ void __launch_bounds__(256, 1) rnn_recur(
    const float* __restrict__ pre,        // [B][T][D]
    const float* __restrict__ Whh,        // [D][D]
    __nv_bfloat16* __restrict__ houtH,    // [B][T][D]
    __nv_bfloat16* __restrict__ houtL)
{
    float4* Wsm = (float4*)smem_r;
    float*  hA  = smem_r + 256 * WPITCH4 * 4;
    float*  hB  = hA + 256;

    int b = blockIdx.x;
    int j = threadIdx.x;

    float4 wr[WREG];
    {
        const float4* wrow = (const float4*)(Whh + (size_t)j * 256);
#pragma unroll
        for (int q = 0; q < WREG; q++) wr[q] = wrow[q];
    }
    for (int i = j; i < 256 * WSMQ; i += 256) {
        int r = i >> 4, c = i & 15;
        Wsm[r * WPITCH4 + c] =
            ((const float4*)(Whh + (size_t)r * 256 + WREG * 4))[c];
    }

    hA[j] = 0.f;
    __syncthreads();

    const float*   prow = pre   + ((size_t)b * Tn) * Dn;
    __nv_bfloat16* ohr  = houtH + ((size_t)b * Tn) * Dn;
    __nv_bfloat16* olr  = houtL + ((size_t)b * Tn) * Dn;
    const float4*  wsr  = Wsm + j * WPITCH4;

    float pcur = prow[j];

#pragma unroll 1
    for (int step = 0; step < Tn; step += 2) {
        {
            float pnext = prow[Dn + j];
            float s = rnn_dot(wr, wsr, (const float4*)hA);
            float v = fast_tanh(pcur + s);
            hB[j] = v;
            __syncthreads();
            // deferred global emit: overlaps next sub-step's dot issue
            __nv_bfloat16 vh = __float2bfloat16(v);
            ohr[j] = vh;
            olr[j] = __float2bfloat16(v - __bfloat162float(vh));
            pcur = pnext; prow += Dn; ohr += Dn; olr += Dn;
        }
        {
            float pnext = (step + 2 < Tn) ? prow[Dn + j] : 0.f;
            float s = rnn_dot(wr, wsr, (const float4*)hB);
            float v = fast_tanh(pcur + s);
            hA[j] = v;
            __syncthreads();
            __nv_bfloat16 vh = __float2bfloat16(v);
            ohr[j] = vh;
            olr[j] = __float2bfloat16(v - __bfloat162float(vh));
            pcur = pnext; prow += Dn; ohr += Dn; olr += Dn;
        }
    }
}

// ---------------------------------------------------------------------------
extern "C" void kernel_launch(void* const* d_in, const int* in_sizes, int n_in,
                              void* d_out, int out_size)
{
    (void)in_sizes; (void)n_in; (void)out_size;

    const int*   ids   = (const int*)  d_in[0];
    const float* emb   = (const float*)d_in[1];
    const float* Wih0  = (const float*)d_in[2];
    const float* Whh0  = (const float*)d_in[3];
    const float* bih0  = (const float*)d_in[4];
    const float* bhh0  = (const float*)d_in[5];
    const float* Wih1  = (const float*)d_in[6];
    const float* Whh1  = (const float*)d_in[7];
    const float* bih1  = (const float*)d_in[8];
    const float* bhh1  = (const float*)d_in[9];
    const float* Whead = (const float*)d_in[10];
    float* out = (float*)d_out;

    float *pre;           cudaGetSymbolAddress((void**)&pre,  g_pre);
    __nv_bfloat16 *hH;    cudaGetSymbolAddress((void**)&hH,   g_hH);
    __nv_bfloat16 *hL;    cudaGetSymbolAddress((void**)&hL,   g_hL);
    __nv_bfloat16 *embH;  cudaGetSymbolAddress((void**)&embH, g_embH);
    __nv_bfloat16 *embL;  cudaGetSymbolAddress((void**)&embL, g_embL);
    __nv_bfloat16 *w0H;   cudaGetSymbolAddress((void**)&w0H,  g_w0H);
    __nv_bfloat16 *w0L;   cudaGetSymbolAddress((void**)&w0L,  g_w0L);
    __nv_bfloat16 *w1H;   cudaGetSymbolAddress((void**)&w1H,  g_w1H);
    __nv_bfloat16 *w1L;   cudaGetSymbolAddress((void**)&w1L,  g_w1L);
    __nv_bfloat16 *whH;   cudaGetSymbolAddress((void**)&whH,  g_whH);
    __nv_bfloat16 *whL;   cudaGetSymbolAddress((void**)&whL,  g_whL);

    const int recur_smem = (256 * WPITCH4 * 4 + 512) * 4;   // 71680 B
    cudaFuncSetAttribute(rnn_recur, cudaFuncAttributeMaxDynamicSharedMemorySize,
                         recur_smem);
    cudaFuncSetAttribute(gemm_mma, cudaFuncAttributeMaxDynamicSharedMemorySize,
                         GEMM_SMEM);

    // Weight / embedding bf16 hi-lo splits
    conv_split<<<(Vn * Dn + 255) / 256, 256>>>(emb,   embH, embL, Vn * Dn);
    conv_split<<<(Dn * Dn + 255) / 256, 256>>>(Wih0,  w0H,  w0L,  Dn * Dn);
    conv_split<<<(Dn * Dn + 255) / 256, 256>>>(Wih1,  w1H,  w1L,  Dn * Dn);
    conv_split<<<(Sn * Dn + 255) / 256, 256>>>(Whead, whH,  whL,  Sn * Dn);

    const int M = Bn * Tn;   // 65536

    // pre0 = emb[ids] @ W_ih0^T + (b_ih0 + b_hh0)
    gemm_mma<<<M / 128, 256, GEMM_SMEM>>>(embH, embL, ids, w0H, w0L,
                                          bih0, bhh0, pre, Dn);
    // h1 recurrence (emits bf16 hi/lo)
    rnn_recur<<<Bn, 256, recur_smem>>>(pre, Whh0, hH, hL);
    // pre1 = h1 @ W_ih1^T + (b_ih1 + b_hh1)
    gemm_mma<<<M / 128, 256, GEMM_SMEM>>>(hH, hL, nullptr, w1H, w1L,
                                          bih1, bhh1, pre, Dn);
    // h2 recurrence
    rnn_recur<<<Bn, 256, recur_smem>>>(pre, Whh1, hH, hL);
    // logits = h2 @ W_head^T
    gemm_mma<<<M / 128, 256, GEMM_SMEM>>>(hH, hL, nullptr, whH, whL,
                                          nullptr, nullptr, out, Sn);
}